// round 8
// baseline (speedup 1.0000x reference)
#include <cuda_runtime.h>
#include <math.h>

#define NN 4
#define CC 64
#define HH 256
#define WW 256
#define OC 18          // G*K*K
#define HW (HH*WW)
#define EPSF 1e-5f

// Scratch (device globals; zero-initialized at load, kept zero by k_stats).
__device__ float g_sigma[(size_t)NN * OC * HW];   // ~18.9 MB
__device__ float g_sum[OC], g_sumsq[OC], g_mean[OC], g_rstd[OC];

#define FMA_F32X2(d, a, b, c) \
    asm("fma.rn.f32x2 %0, %1, %2, %3;" : "=l"(d) : "l"(a), "l"(b), "l"(c))

__device__ __forceinline__ unsigned long long pack2(float v) {
    unsigned long long r;
    asm("mov.b64 %0, {%1, %1};" : "=l"(r) : "r"(__float_as_uint(v)));
    return r;
}
__device__ __forceinline__ float lo2(unsigned long long v) { return __uint_as_float((unsigned)v); }
__device__ __forceinline__ float hi2(unsigned long long v) { return __uint_as_float((unsigned)(v >> 32)); }

// jnp.pad mode='reflect' (mirror, edge not repeated)
__device__ __forceinline__ int refl(int i, int n) {
    return i < 0 ? -i : (i >= n ? 2 * n - 2 - i : i);
}

// ---------------------------------------------------------------------------
// Stage 1: 3x3 conv (64 -> 18 ch, reflect) + BN stats.
// 4 pixels/thread; output channels split across warp-pairs: warps ty<2 do
// outs [0,10) (NP=5 packed), ty>=2 do outs [10,18) (NP=4). Weights staged in
// SMEM in two 32-channel phases (23KB) so 5 CTAs/SM fit.
// ws layout: [(c_local*9+t)*20 + off], halfA floats 0..9, halfB floats 12..19.
// ---------------------------------------------------------------------------

template<int NP>
__device__ __forceinline__ void tap4(const float* wp,
                                     unsigned long long va, unsigned long long vb,
                                     unsigned long long vc, unsigned long long vd,
                                     unsigned long long* acc) {
    unsigned long long w[NP];
    ulonglong2 w01 = *(const ulonglong2*)wp;
    ulonglong2 w23 = *(const ulonglong2*)(wp + 4);
    w[0] = w01.x; w[1] = w01.y; w[2] = w23.x; w[3] = w23.y;
    if (NP == 5) w[4] = *(const unsigned long long*)(wp + 8);
#pragma unroll
    for (int q = 0; q < NP; q++) {
        FMA_F32X2(acc[q],          va, w[q], acc[q]);
        FMA_F32X2(acc[NP + q],     vb, w[q], acc[NP + q]);
        FMA_F32X2(acc[2 * NP + q], vc, w[q], acc[2 * NP + q]);
        FMA_F32X2(acc[3 * NP + q], vd, w[q], acc[3 * NP + q]);
    }
}

// One image row: mid tap (j=1) first, then j=0 / j=2 (edge scalars L1-hit).
template<int NP>
__device__ __forceinline__ void row4(float4 m, float el, float er,
                                     const float* wrow, unsigned long long* acc) {
    unsigned long long v1 = pack2(m.x), v2 = pack2(m.y);
    unsigned long long v3 = pack2(m.z), v4 = pack2(m.w);
    tap4<NP>(wrow + 20, v1, v2, v3, v4, acc);
    unsigned long long v0 = pack2(el);
    tap4<NP>(wrow, v0, v1, v2, v3, acc);
    unsigned long long v5 = pack2(er);
    tap4<NP>(wrow + 40, v2, v3, v4, v5, acc);
}

template<int NP, int WOFF>
__device__ __forceinline__ void proc32(const float* ybase, const float* ws,
                                       int om0, int om1, int om2,
                                       int ol0, int ol1, int ol2,
                                       int or0, int or1, int or2,
                                       unsigned long long* acc) {
    const float* yc = ybase;
#pragma unroll 2
    for (int c = 0; c < 32; c++) {
        float4 m0 = __ldg((const float4*)(yc + om0));
        float4 m1 = __ldg((const float4*)(yc + om1));
        float4 m2 = __ldg((const float4*)(yc + om2));
        float el0 = __ldg(yc + ol0), er0 = __ldg(yc + or0);
        float el1 = __ldg(yc + ol1), er1 = __ldg(yc + or1);
        float el2 = __ldg(yc + ol2), er2 = __ldg(yc + or2);

        const float* wr0 = ws + c * 180 + WOFF;
        row4<NP>(m0, el0, er0, wr0,       acc);
        row4<NP>(m1, el1, er1, wr0 + 60,  acc);
        row4<NP>(m2, el2, er2, wr0 + 120, acc);
        yc += HW;
    }
}

template<int NP, int OBASE>
__device__ __forceinline__ void finish(const unsigned long long* acc, int n, size_t pix,
                                       float* ssum, float* ssq, int lane) {
#pragma unroll
    for (int o = 0; o < 2 * NP; o++) {
        int u = o >> 1;
        float4 vv;
        if (o & 1)
            vv = make_float4(hi2(acc[u]), hi2(acc[NP + u]),
                             hi2(acc[2 * NP + u]), hi2(acc[3 * NP + u]));
        else
            vv = make_float4(lo2(acc[u]), lo2(acc[NP + u]),
                             lo2(acc[2 * NP + u]), lo2(acc[3 * NP + u]));
        *(float4*)&g_sigma[((size_t)n * OC + OBASE + o) * HW + pix] = vv;

        float s = vv.x + vv.y + vv.z + vv.w;
        float q = vv.x * vv.x + vv.y * vv.y + vv.z * vv.z + vv.w * vv.w;
#pragma unroll
        for (int off = 16; off; off >>= 1) {
            s += __shfl_down_sync(0xffffffffu, s, off);
            q += __shfl_down_sync(0xffffffffu, q, off);
        }
        if (lane == 0) { atomicAdd(&ssum[OBASE + o], s); atomicAdd(&ssq[OBASE + o], q); }
    }
}

__global__ void __launch_bounds__(128, 5) k_conv(const float* __restrict__ y,
                                                 const float* __restrict__ wconv) {
    __shared__ __align__(16) float ws[32 * 9 * 20];   // 23040 B
    __shared__ float ssum[OC], ssq[OC];

    int tx = threadIdx.x, ty = threadIdx.y;
    int tid = ty * 32 + tx;
    int half = ty >> 1;

    if (tid < OC) { ssum[tid] = 0.f; ssq[tid] = 0.f; }

    int w0 = (blockIdx.x * 32 + tx) * 4;
    int h0 = blockIdx.y * 2 + (ty & 1);
    int n  = blockIdx.z;

    int rh[3];
#pragma unroll
    for (int i = 0; i < 3; i++) rh[i] = refl(h0 + i - 1, HH);
    int wl = refl(w0 - 1, WW);
    int wr = refl(w0 + 4, WW);

    int om0 = rh[0] * WW + w0, om1 = rh[1] * WW + w0, om2 = rh[2] * WW + w0;
    int ol0 = rh[0] * WW + wl, ol1 = rh[1] * WW + wl, ol2 = rh[2] * WW + wl;
    int or0 = rh[0] * WW + wr, or1 = rh[1] * WW + wr, or2 = rh[2] * WW + wr;

    unsigned long long acc[20];
#pragma unroll
    for (int p = 0; p < 20; p++) acc[p] = 0ull;

    for (int ph = 0; ph < 2; ph++) {
        __syncthreads();
        // stage 32 channels: ws[ct*20 + map(o)] = w[o][ph*32 + ct/9][ct%9]
        for (int i = tid; i < 32 * 9 * OC; i += 128) {
            int o = i % OC, ct = i / OC;
            int oo = (o < 10) ? o : o + 2;   // halfB at offset 12 (16B aligned)
            ws[ct * 20 + oo] = wconv[((size_t)o * CC + ph * 32 + ct / 9) * 9 + (ct % 9)];
        }
        __syncthreads();

        const float* ybase = y + ((size_t)n * CC + ph * 32) * HW;
        if (half == 0)
            proc32<5, 0>(ybase, ws, om0, om1, om2, ol0, ol1, ol2, or0, or1, or2, acc);
        else
            proc32<4, 12>(ybase, ws, om0, om1, om2, ol0, ol1, ol2, or0, or1, or2, acc);
    }

    size_t pix = (size_t)h0 * WW + w0;
    if (half == 0) finish<5, 0>(acc, n, pix, ssum, ssq, tx);
    else           finish<4, 10>(acc, n, pix, ssum, ssq, tx);

    __syncthreads();
    if (tid < OC) { atomicAdd(&g_sum[tid], ssum[tid]); atomicAdd(&g_sumsq[tid], ssq[tid]); }
}

// Stats + self-reset (next graph replay sees zeros again).
__global__ void k_stats() {
    int o = threadIdx.x;
    if (o < OC) {
        float cnt = (float)((size_t)NN * HW);
        float m = g_sum[o] / cnt;
        float v = g_sumsq[o] / cnt - m * m;
        g_mean[o] = m;
        g_rstd[o] = rsqrtf(v + EPSF);
        g_sum[o] = 0.f;
        g_sumsq[o] = 0.f;
    }
}

// ---------------------------------------------------------------------------
// Stage 3: BN + softmax(18) + v_map + adaptive 3x3 filter. 2 pixels/thread
// (higher occupancy / MLP for this DRAM-latency-bound kernel).
// ---------------------------------------------------------------------------
__global__ void __launch_bounds__(128) k_apply(const float* __restrict__ y,
                                               const float* __restrict__ gamma,
                                               const float* __restrict__ beta,
                                               float* __restrict__ out) {
    int tx = threadIdx.x, ty = threadIdx.y;
    int w0 = (blockIdx.x * 32 + tx) * 2;
    int h0 = blockIdx.y * 4 + ty;
    int n  = blockIdx.z;
    size_t pix = (size_t)h0 * WW + w0;

    float2 s2[OC];
    float2 mx = make_float2(-1e30f, -1e30f);
#pragma unroll
    for (int o = 0; o < OC; o++) {
        float2 x = *(const float2*)&g_sigma[((size_t)n * OC + o) * HW + pix];
        float sc = g_rstd[o] * __ldg(&gamma[o]);
        float m  = g_mean[o], b = __ldg(&beta[o]);
        x.x = (x.x - m) * sc + b;
        x.y = (x.y - m) * sc + b;
        s2[o] = x;
        mx.x = fmaxf(mx.x, x.x); mx.y = fmaxf(mx.y, x.y);
    }
    float2 sum = make_float2(0.f, 0.f);
#pragma unroll
    for (int o = 0; o < OC; o++) {
        s2[o].x = __expf(s2[o].x - mx.x); sum.x += s2[o].x;
        s2[o].y = __expf(s2[o].y - mx.y); sum.y += s2[o].y;
    }
    float2 inv = make_float2(1.f / sum.x, 1.f / sum.y);
#pragma unroll
    for (int o = 0; o < OC; o++) { s2[o].x *= inv.x; s2[o].y *= inv.y; }

    float* vmap = out + (size_t)NN * CC * HW;
#pragma unroll
    for (int o = 0; o < OC; o++)
        *(float2*)&vmap[((size_t)n * OC + o) * HW + pix] = s2[o];

    int rh[3];
#pragma unroll
    for (int i = 0; i < 3; i++) rh[i] = refl(h0 + i - 1, HH);
    int wl = refl(w0 - 1, WW);
    int wr = refl(w0 + 2, WW);

#pragma unroll
    for (int g = 0; g < 2; g++) {
#pragma unroll 2
        for (int cg = 0; cg < 32; cg++) {
            int c = g * 32 + cg;
            const float* yc = y + ((size_t)(n * CC + c)) * HW;
            float2 acc = make_float2(0.f, 0.f);
#pragma unroll
            for (int i = 0; i < 3; i++) {
                const float* row = yc + rh[i] * WW;
                float2 m = __ldg((const float2*)(row + w0));
                float v[4];
                v[0] = __ldg(&row[wl]); v[1] = m.x; v[2] = m.y;
                v[3] = __ldg(&row[wr]);
#pragma unroll
                for (int j = 0; j < 3; j++) {
                    float2 sw = s2[g * 9 + i * 3 + j];
                    acc.x += v[0 + j] * sw.x;
                    acc.y += v[1 + j] * sw.y;
                }
            }
            *(float2*)&out[((size_t)(n * CC + c)) * HW + pix] = acc;
        }
    }
}

extern "C" void kernel_launch(void* const* d_in, const int* in_sizes, int n_in,
                              void* d_out, int out_size) {
    const float* y     = (const float*)d_in[0];
    const float* w     = (const float*)d_in[1];
    const float* gamma = (const float*)d_in[2];
    const float* beta  = (const float*)d_in[3];
    float* out = (float*)d_out;

    dim3 cblk(32, 4), cgrd(WW / 128, HH / 2, NN);   // 2 x 128 x 4 = 1024 CTAs
    k_conv<<<cgrd, cblk>>>(y, w);
    k_stats<<<1, 32>>>();

    dim3 ablk(32, 4), agrd(WW / 64, HH / 4, NN);    // 1024 CTAs
    k_apply<<<agrd, ablk>>>(y, gamma, beta, out);
}

// round 9
// speedup vs baseline: 1.0804x; 1.0804x over previous
#include <cuda_runtime.h>
#include <math.h>

#define NN 4
#define CC 64
#define HH 256
#define WW 256
#define OC 18          // G*K*K
#define HW (HH*WW)
#define EPSF 1e-5f

// Scratch (device globals; zero-initialized at load, kept zero by k_stats).
__device__ float g_sigma[(size_t)NN * OC * HW];   // ~18.9 MB
__device__ float g_sum[OC], g_sumsq[OC], g_mean[OC], g_rstd[OC];

#define FMA_F32X2(d, a, b, c) \
    asm("fma.rn.f32x2 %0, %1, %2, %3;" : "=l"(d) : "l"(a), "l"(b), "l"(c))

__device__ __forceinline__ unsigned long long pack2(float v) {
    unsigned long long r;
    asm("mov.b64 %0, {%1, %1};" : "=l"(r) : "r"(__float_as_uint(v)));
    return r;
}
__device__ __forceinline__ float lo2(unsigned long long v) { return __uint_as_float((unsigned)v); }
__device__ __forceinline__ float hi2(unsigned long long v) { return __uint_as_float((unsigned)(v >> 32)); }

// jnp.pad mode='reflect' (mirror, edge not repeated)
__device__ __forceinline__ int refl(int i, int n) {
    return i < 0 ? -i : (i >= n ? 2 * n - 2 - i : i);
}

// ---------------------------------------------------------------------------
// Stage 1: 3x3 conv (64 -> 18 ch, reflect) + BN stats.
// 4 pixels/thread, 9 packed FFMA2 accumulators per pixel, prefetched channel
// loop. Channel order rotated per warp (cstart) to desynchronize co-resident
// warps' load/FMA phases (lockstep-starvation fix).
// ---------------------------------------------------------------------------

// One tap: 9 packed weights vs 4 pixels' broadcast values va..vd.
#define TAP(wp, va, vb, vc, vd)                                                \
    {                                                                          \
        ulonglong2 w01 = *(const ulonglong2*)((wp));                           \
        ulonglong2 w23 = *(const ulonglong2*)((wp) + 4);                       \
        ulonglong2 w45 = *(const ulonglong2*)((wp) + 8);                       \
        ulonglong2 w67 = *(const ulonglong2*)((wp) + 12);                      \
        unsigned long long w8 = *(const unsigned long long*)((wp) + 16);       \
        FMA_F32X2(acc2[0], va, w01.x, acc2[0]);                                \
        FMA_F32X2(acc2[1], va, w01.y, acc2[1]);                                \
        FMA_F32X2(acc2[2], va, w23.x, acc2[2]);                                \
        FMA_F32X2(acc2[3], va, w23.y, acc2[3]);                                \
        FMA_F32X2(acc2[4], va, w45.x, acc2[4]);                                \
        FMA_F32X2(acc2[5], va, w45.y, acc2[5]);                                \
        FMA_F32X2(acc2[6], va, w67.x, acc2[6]);                                \
        FMA_F32X2(acc2[7], va, w67.y, acc2[7]);                                \
        FMA_F32X2(acc2[8], va, w8,    acc2[8]);                                \
        FMA_F32X2(acc2[9],  vb, w01.x, acc2[9]);                               \
        FMA_F32X2(acc2[10], vb, w01.y, acc2[10]);                              \
        FMA_F32X2(acc2[11], vb, w23.x, acc2[11]);                              \
        FMA_F32X2(acc2[12], vb, w23.y, acc2[12]);                              \
        FMA_F32X2(acc2[13], vb, w45.x, acc2[13]);                              \
        FMA_F32X2(acc2[14], vb, w45.y, acc2[14]);                              \
        FMA_F32X2(acc2[15], vb, w67.x, acc2[15]);                              \
        FMA_F32X2(acc2[16], vb, w67.y, acc2[16]);                              \
        FMA_F32X2(acc2[17], vb, w8,    acc2[17]);                              \
        FMA_F32X2(acc2[18], vc, w01.x, acc2[18]);                              \
        FMA_F32X2(acc2[19], vc, w01.y, acc2[19]);                              \
        FMA_F32X2(acc2[20], vc, w23.x, acc2[20]);                              \
        FMA_F32X2(acc2[21], vc, w23.y, acc2[21]);                              \
        FMA_F32X2(acc2[22], vc, w45.x, acc2[22]);                              \
        FMA_F32X2(acc2[23], vc, w45.y, acc2[23]);                              \
        FMA_F32X2(acc2[24], vc, w67.x, acc2[24]);                              \
        FMA_F32X2(acc2[25], vc, w67.y, acc2[25]);                              \
        FMA_F32X2(acc2[26], vc, w8,    acc2[26]);                              \
        FMA_F32X2(acc2[27], vd, w01.x, acc2[27]);                              \
        FMA_F32X2(acc2[28], vd, w01.y, acc2[28]);                              \
        FMA_F32X2(acc2[29], vd, w23.x, acc2[29]);                              \
        FMA_F32X2(acc2[30], vd, w23.y, acc2[30]);                              \
        FMA_F32X2(acc2[31], vd, w45.x, acc2[31]);                              \
        FMA_F32X2(acc2[32], vd, w45.y, acc2[32]);                              \
        FMA_F32X2(acc2[33], vd, w67.x, acc2[33]);                              \
        FMA_F32X2(acc2[34], vd, w67.y, acc2[34]);                              \
        FMA_F32X2(acc2[35], vd, w8,    acc2[35]);                              \
    }

// One image row: mid tap (j=1) first, then j=0 / j=2 (edge scalars L1-hit).
#define ROW(m, el, er, wrow3)                                                  \
    {                                                                          \
        unsigned long long v1 = pack2((m).x), v2 = pack2((m).y);               \
        unsigned long long v3 = pack2((m).z), v4 = pack2((m).w);               \
        TAP((wrow3) + 20, v1, v2, v3, v4)                                      \
        unsigned long long v0 = pack2(el);                                     \
        TAP((wrow3), v0, v1, v2, v3)                                           \
        unsigned long long v5 = pack2(er);                                     \
        TAP((wrow3) + 40, v2, v3, v4, v5)                                      \
    }

__global__ void __launch_bounds__(128, 4) k_conv(const float* __restrict__ y,
                                                 const float* __restrict__ wconv) {
    __shared__ __align__(16) float ws[CC * 9 * 20];   // 46080 B
    __shared__ float ssum[OC], ssq[OC];

    int tx = threadIdx.x, ty = threadIdx.y;
    int tid = ty * 32 + tx;

    if (tid < OC) { ssum[tid] = 0.f; ssq[tid] = 0.f; }
    for (int i = tid; i < CC * 9 * OC; i += 128) {
        int o = i % OC, ct = i / OC;
        ws[ct * 20 + o] = wconv[((size_t)o * CC + ct / 9) * 9 + (ct % 9)];
    }
    __syncthreads();

    int w0 = (blockIdx.x * 32 + tx) * 4;
    int h0 = blockIdx.y * 4 + ty;
    int n  = blockIdx.z;

    int rh[3];
#pragma unroll
    for (int i = 0; i < 3; i++) rh[i] = refl(h0 + i - 1, HH);
    int wl = refl(w0 - 1, WW);
    int wr = refl(w0 + 4, WW);

    int om0 = rh[0] * WW + w0, om1 = rh[1] * WW + w0, om2 = rh[2] * WW + w0;
    int ol0 = rh[0] * WW + wl, ol1 = rh[1] * WW + wl, ol2 = rh[2] * WW + wl;
    int or0 = rh[0] * WW + wr, or1 = rh[1] * WW + wr, or2 = rh[2] * WW + wr;

    unsigned long long acc2[36];
#pragma unroll
    for (int p = 0; p < 36; p++) acc2[p] = 0ull;

    const float* ybase = y + ((size_t)n * CC) * HW;

    // Per-warp channel-order rotation: desync co-resident warps (keyed on
    // blockIdx too, since all CTAs on one SMSP share the same ty).
    int cstart = ((blockIdx.x + blockIdx.y + ty) & 3) * 16;

    int ce = cstart;
    const float* yc = ybase + (size_t)ce * HW;
    float4 cm0 = __ldg((const float4*)(yc + om0));
    float4 cm1 = __ldg((const float4*)(yc + om1));
    float4 cm2 = __ldg((const float4*)(yc + om2));

#pragma unroll 2
    for (int c = 0; c < CC; c++) {
        // next channel in rotated order (last iter: reload current, discarded)
        int cn = (c < CC - 1) ? ((c + 1 + cstart) & 63) : ce;
        const float* ycn = ybase + (size_t)cn * HW;
        float4 nm0 = __ldg((const float4*)(ycn + om0));
        float4 nm1 = __ldg((const float4*)(ycn + om1));
        float4 nm2 = __ldg((const float4*)(ycn + om2));

        float el0 = __ldg(yc + ol0), er0 = __ldg(yc + or0);
        float el1 = __ldg(yc + ol1), er1 = __ldg(yc + or1);
        float el2 = __ldg(yc + ol2), er2 = __ldg(yc + or2);

        const float* wrow = &ws[ce * 180];
        ROW(cm0, el0, er0, wrow)
        ROW(cm1, el1, er1, wrow + 60)
        ROW(cm2, el2, er2, wrow + 120)

        yc = ycn; ce = cn;
        cm0 = nm0; cm1 = nm1; cm2 = nm2;
    }

    size_t pix = (size_t)h0 * WW + w0;
#pragma unroll
    for (int o = 0; o < OC; o++) {
        int u = o >> 1;
        float4 vv;
        if (o & 1) {
            vv = make_float4(hi2(acc2[u]), hi2(acc2[9 + u]),
                             hi2(acc2[18 + u]), hi2(acc2[27 + u]));
        } else {
            vv = make_float4(lo2(acc2[u]), lo2(acc2[9 + u]),
                             lo2(acc2[18 + u]), lo2(acc2[27 + u]));
        }
        *(float4*)&g_sigma[((size_t)n * OC + o) * HW + pix] = vv;

        float s = vv.x + vv.y + vv.z + vv.w;
        float q = vv.x * vv.x + vv.y * vv.y + vv.z * vv.z + vv.w * vv.w;
#pragma unroll
        for (int off = 16; off; off >>= 1) {
            s += __shfl_down_sync(0xffffffffu, s, off);
            q += __shfl_down_sync(0xffffffffu, q, off);
        }
        if ((tid & 31) == 0) { atomicAdd(&ssum[o], s); atomicAdd(&ssq[o], q); }
    }
    __syncthreads();
    if (tid < OC) { atomicAdd(&g_sum[tid], ssum[tid]); atomicAdd(&g_sumsq[tid], ssq[tid]); }
}

// Stats + self-reset (next graph replay sees zeros again).
__global__ void k_stats() {
    int o = threadIdx.x;
    if (o < OC) {
        float cnt = (float)((size_t)NN * HW);
        float m = g_sum[o] / cnt;
        float v = g_sumsq[o] / cnt - m * m;
        g_mean[o] = m;
        g_rstd[o] = rsqrtf(v + EPSF);
        g_sum[o] = 0.f;
        g_sumsq[o] = 0.f;
    }
}

// ---------------------------------------------------------------------------
// Stage 3: BN + softmax(18) + v_map + adaptive 3x3 filter. 4 pixels/thread
// (the measured-best variant).
// ---------------------------------------------------------------------------
__global__ void __launch_bounds__(128) k_apply(const float* __restrict__ y,
                                               const float* __restrict__ gamma,
                                               const float* __restrict__ beta,
                                               float* __restrict__ out) {
    int tx = threadIdx.x, ty = threadIdx.y;
    int w0 = (blockIdx.x * 32 + tx) * 4;
    int h0 = blockIdx.y * 4 + ty;
    int n  = blockIdx.z;
    size_t pix = (size_t)h0 * WW + w0;

    float4 s4[OC];
    float4 mx = make_float4(-1e30f, -1e30f, -1e30f, -1e30f);
#pragma unroll
    for (int o = 0; o < OC; o++) {
        float4 x = *(const float4*)&g_sigma[((size_t)n * OC + o) * HW + pix];
        float sc = g_rstd[o] * __ldg(&gamma[o]);
        float m  = g_mean[o], b = __ldg(&beta[o]);
        x.x = (x.x - m) * sc + b; x.y = (x.y - m) * sc + b;
        x.z = (x.z - m) * sc + b; x.w = (x.w - m) * sc + b;
        s4[o] = x;
        mx.x = fmaxf(mx.x, x.x); mx.y = fmaxf(mx.y, x.y);
        mx.z = fmaxf(mx.z, x.z); mx.w = fmaxf(mx.w, x.w);
    }
    float4 sum = make_float4(0.f, 0.f, 0.f, 0.f);
#pragma unroll
    for (int o = 0; o < OC; o++) {
        s4[o].x = __expf(s4[o].x - mx.x); sum.x += s4[o].x;
        s4[o].y = __expf(s4[o].y - mx.y); sum.y += s4[o].y;
        s4[o].z = __expf(s4[o].z - mx.z); sum.z += s4[o].z;
        s4[o].w = __expf(s4[o].w - mx.w); sum.w += s4[o].w;
    }
    float4 inv = make_float4(1.f / sum.x, 1.f / sum.y, 1.f / sum.z, 1.f / sum.w);
#pragma unroll
    for (int o = 0; o < OC; o++) {
        s4[o].x *= inv.x; s4[o].y *= inv.y; s4[o].z *= inv.z; s4[o].w *= inv.w;
    }

    float* vmap = out + (size_t)NN * CC * HW;
#pragma unroll
    for (int o = 0; o < OC; o++)
        *(float4*)&vmap[((size_t)n * OC + o) * HW + pix] = s4[o];

    int rh[3];
#pragma unroll
    for (int i = 0; i < 3; i++) rh[i] = refl(h0 + i - 1, HH);
    int wl = refl(w0 - 1, WW);
    int wr = refl(w0 + 4, WW);

#pragma unroll
    for (int g = 0; g < 2; g++) {
#pragma unroll 2
        for (int cg = 0; cg < 32; cg++) {
            int c = g * 32 + cg;
            const float* yc = y + ((size_t)(n * CC + c)) * HW;
            float4 acc = make_float4(0.f, 0.f, 0.f, 0.f);
#pragma unroll
            for (int i = 0; i < 3; i++) {
                const float* row = yc + rh[i] * WW;
                float4 m = __ldg((const float4*)(row + w0));
                float v[6];
                v[0] = __ldg(&row[wl]); v[1] = m.x; v[2] = m.y;
                v[3] = m.z; v[4] = m.w; v[5] = __ldg(&row[wr]);
#pragma unroll
                for (int j = 0; j < 3; j++) {
                    float4 sw = s4[g * 9 + i * 3 + j];
                    acc.x += v[0 + j] * sw.x;
                    acc.y += v[1 + j] * sw.y;
                    acc.z += v[2 + j] * sw.z;
                    acc.w += v[3 + j] * sw.w;
                }
            }
            *(float4*)&out[((size_t)(n * CC + c)) * HW + pix] = acc;
        }
    }
}

extern "C" void kernel_launch(void* const* d_in, const int* in_sizes, int n_in,
                              void* d_out, int out_size) {
    const float* y     = (const float*)d_in[0];
    const float* w     = (const float*)d_in[1];
    const float* gamma = (const float*)d_in[2];
    const float* beta  = (const float*)d_in[3];
    float* out = (float*)d_out;

    dim3 cblk(32, 4), cgrd(WW / 128, HH / 4, NN);   // 512 CTAs
    k_conv<<<cgrd, cblk>>>(y, w);
    k_stats<<<1, 32>>>();

    dim3 ablk(32, 4), agrd(WW / 128, HH / 4, NN);
    k_apply<<<agrd, ablk>>>(y, gamma, beta, out);
}

// round 10
// speedup vs baseline: 1.1885x; 1.1000x over previous
#include <cuda_runtime.h>
#include <math.h>

#define NN 4
#define CC 64
#define HH 256
#define WW 256
#define OC 18          // G*K*K
#define HW (HH*WW)
#define EPSF 1e-5f

// Scratch (device globals; zero-initialized at load, kept zero by k_stats).
__device__ float g_sigma[(size_t)NN * OC * HW];   // ~18.9 MB
__device__ float g_sum[OC], g_sumsq[OC], g_mean[OC], g_rstd[OC];

// Pre-split weights: packed bf16 pairs (consecutive-k), hi and lo (residual).
// Layout: [pair_row][o], pair_row = kp/2 over padded K' = 8 kblocks * 80 = 640.
__device__ unsigned g_Bph[320 * 24];
__device__ unsigned g_Bpl[320 * 24];

// jnp.pad mode='reflect' (mirror, edge not repeated)
__device__ __forceinline__ int refl(int i, int n) {
    return i < 0 ? -i : (i >= n ? 2 * n - 2 - i : i);
}

// pack two f32 -> bf16x2; LOWER half = v0 (PTX: upper operand listed first)
__device__ __forceinline__ unsigned bfpack(float v0, float v1) {
    unsigned r;
    asm("cvt.rn.bf16x2.f32 %0, %1, %2;" : "=r"(r) : "f"(v1), "f"(v0));
    return r;
}
__device__ __forceinline__ float bflo(unsigned p) { return __uint_as_float(p << 16); }
__device__ __forceinline__ float bfhi(unsigned p) { return __uint_as_float(p & 0xFFFF0000u); }

#define MMA16816(d, a, b)                                                      \
    asm volatile(                                                              \
        "mma.sync.aligned.m16n8k16.row.col.f32.bf16.bf16.f32 "                 \
        "{%0,%1,%2,%3},{%4,%5,%6,%7},{%8,%9},{%0,%1,%2,%3};"                   \
        : "+f"(d[0]), "+f"(d[1]), "+f"(d[2]), "+f"(d[3])                       \
        : "r"(a[0]), "r"(a[1]), "r"(a[2]), "r"(a[3]), "r"(b[0]), "r"(b[1]))

// ---------------------------------------------------------------------------
// Weight prep: B[k][o] with k = c*9+t padded per-8ch-block to 80, split into
// bf16 hi + residual lo, packed as consecutive-k pairs.
// ---------------------------------------------------------------------------
__device__ __forceinline__ float wval(const float* w, int kp, int o) {
    int kb = kp / 80, r = kp % 80;
    if (r >= 72 || o >= OC) return 0.f;
    int c = kb * 8 + r / 9, t = r % 9;
    return w[((size_t)o * CC + c) * 9 + t];
}

__global__ void k_wprep(const float* __restrict__ w) {
    int idx = blockIdx.x * 256 + threadIdx.x;
    if (idx >= 320 * 24) return;
    int kp2 = idx / 24, o = idx % 24;
    float v0 = wval(w, 2 * kp2, o), v1 = wval(w, 2 * kp2 + 1, o);
    unsigned hi = bfpack(v0, v1);
    unsigned lo = bfpack(v0 - bflo(hi), v1 - bfhi(hi));
    g_Bph[idx] = hi;
    g_Bpl[idx] = lo;
}

// ---------------------------------------------------------------------------
// Conv via mma.sync bf16 (3-term split). CTA = 128 threads, 128-px row strip.
// Warp: 32 px (2 m16 tiles) x 24 outs (3 n8 tiles). K loop: 8 blocks of 8
// channels (72 k padded to 80 = 5 k16 chunks; pad k reads the zeroed 9th
// y_s channel slot via lut).
// ---------------------------------------------------------------------------
#define YSC 132            // y_s col stride (cols 0..129 used; col0 = w0-1)
#define YSCH (3 * YSC)     // 396 floats per channel slot

__global__ void __launch_bounds__(128, 4) k_conv(const float* __restrict__ y) {
    __shared__ float y_s[9 * YSCH];   // 14256 B (slot 8 stays zero)
    __shared__ int lut[80];

    int tid  = threadIdx.x;
    int warp = tid >> 5, lane = tid & 31;
    int g = lane >> 2, t = lane & 3;

    int w0 = blockIdx.x * 128;
    int h  = blockIdx.y;
    int n  = blockIdx.z;

    int rh[3];
#pragma unroll
    for (int r = 0; r < 3; r++) rh[r] = refl(h + r - 1, HH);

    for (int i = tid; i < YSCH; i += 128) y_s[8 * YSCH + i] = 0.f;
    if (tid < 80) {
        int kp = tid, c, tt;
        if (kp < 72) { c = kp / 9; tt = kp % 9; } else { c = 8; tt = 0; }
        lut[tid] = c * YSCH + (tt / 3) * YSC + (tt % 3);
    }

    float acc[2][3][4];
#pragma unroll
    for (int a = 0; a < 2; a++)
#pragma unroll
        for (int b = 0; b < 3; b++)
#pragma unroll
            for (int d = 0; d < 4; d++) acc[a][b][d] = 0.f;

    int px0 = warp * 32 + g;
    int c8 = tid >> 4, s16 = tid & 15;

    for (int kb = 0; kb < 8; kb++) {
        __syncthreads();
        // stage 8 channels x 3 rows x 130(+2) cols, reflect baked in
        const float* ysrc = y + ((size_t)(n * CC + kb * 8 + c8)) * HW;
        for (int q = s16; q < YSCH; q += 16) {
            int r = (q >= 2 * YSC) ? 2 : (q >= YSC ? 1 : 0);
            int col = q - r * YSC;
            int gw = refl(w0 - 1 + col, WW);
            y_s[c8 * YSCH + q] = __ldg(&ysrc[rh[r] * WW + gw]);
        }
        __syncthreads();

        int brow0 = kb * 40;
#pragma unroll
        for (int ch = 0; ch < 5; ch++) {
            int kpA = ch * 16 + 2 * t;
            int oA0 = lut[kpA], oA1 = lut[kpA + 1];
            int oB0 = lut[kpA + 8], oB1 = lut[kpA + 9];

            unsigned ah[2][4], al[2][4];
#pragma unroll
            for (int mt = 0; mt < 2; mt++) {
                int p = px0 + mt * 16;
#pragma unroll
                for (int ar = 0; ar < 4; ar++) {
                    int o0 = (ar & 2) ? oB0 : oA0;
                    int o1 = (ar & 2) ? oB1 : oA1;
                    int pp = p + ((ar & 1) ? 8 : 0);
                    float v0 = y_s[o0 + pp];
                    float v1 = y_s[o1 + pp];
                    unsigned hi = bfpack(v0, v1);
                    ah[mt][ar] = hi;
                    al[mt][ar] = bfpack(v0 - bflo(hi), v1 - bfhi(hi));
                }
            }

            int brow = brow0 + ch * 8 + t;
#pragma unroll
            for (int nt = 0; nt < 3; nt++) {
                int col = nt * 8 + g;
                unsigned bh[2], bl[2];
                bh[0] = g_Bph[brow * 24 + col];
                bh[1] = g_Bph[(brow + 4) * 24 + col];
                bl[0] = g_Bpl[brow * 24 + col];
                bl[1] = g_Bpl[(brow + 4) * 24 + col];
#pragma unroll
                for (int mt = 0; mt < 2; mt++) {
                    MMA16816(acc[mt][nt], ah[mt], bh);
                    MMA16816(acc[mt][nt], al[mt], bh);
                    MMA16816(acc[mt][nt], ah[mt], bl);
                }
            }
        }
    }

    // epilogue: D[g(+8)][2t(+1)] per (mt, nt) -> g_sigma[n][o][h*W + w0 + px]
#pragma unroll
    for (int mt = 0; mt < 2; mt++)
#pragma unroll
        for (int nt = 0; nt < 3; nt++)
#pragma unroll
            for (int dd = 0; dd < 4; dd++) {
                int o = nt * 8 + 2 * t + (dd & 1);
                if (o < OC) {
                    int px = warp * 32 + mt * 16 + g + ((dd & 2) ? 8 : 0);
                    g_sigma[((size_t)n * OC + o) * HW + (size_t)h * WW + w0 + px] =
                        acc[mt][nt][dd];
                }
            }
}

// ---------------------------------------------------------------------------
// BN stats: reduce g_sigma per output channel.
// ---------------------------------------------------------------------------
__global__ void k_sigred() {
    int o = blockIdx.x;           // 0..17
    int slice = blockIdx.y;       // 0..31
    size_t per = ((size_t)NN * HW) / 32;   // 32768
    float s = 0.f, q = 0.f;
    for (size_t i = threadIdx.x; i < per; i += 256) {
        size_t e = (size_t)slice * per + i;
        int nn = (int)(e >> 16);            // / HW
        size_t p = e & (HW - 1);
        float v = g_sigma[((size_t)nn * OC + o) * HW + p];
        s += v; q += v * v;
    }
#pragma unroll
    for (int off = 16; off; off >>= 1) {
        s += __shfl_down_sync(0xffffffffu, s, off);
        q += __shfl_down_sync(0xffffffffu, q, off);
    }
    if ((threadIdx.x & 31) == 0) {
        atomicAdd(&g_sum[o], s);
        atomicAdd(&g_sumsq[o], q);
    }
}

// Stats + self-reset (next graph replay sees zeros again).
__global__ void k_stats() {
    int o = threadIdx.x;
    if (o < OC) {
        float cnt = (float)((size_t)NN * HW);
        float m = g_sum[o] / cnt;
        float v = g_sumsq[o] / cnt - m * m;
        g_mean[o] = m;
        g_rstd[o] = rsqrtf(v + EPSF);
        g_sum[o] = 0.f;
        g_sumsq[o] = 0.f;
    }
}

// ---------------------------------------------------------------------------
// Stage 3: BN + softmax(18) + v_map + adaptive 3x3 filter. 4 pixels/thread.
// ---------------------------------------------------------------------------
__global__ void __launch_bounds__(128) k_apply(const float* __restrict__ y,
                                               const float* __restrict__ gamma,
                                               const float* __restrict__ beta,
                                               float* __restrict__ out) {
    int tx = threadIdx.x, ty = threadIdx.y;
    int w0 = (blockIdx.x * 32 + tx) * 4;
    int h0 = blockIdx.y * 4 + ty;
    int n  = blockIdx.z;
    size_t pix = (size_t)h0 * WW + w0;

    float4 s4[OC];
    float4 mx = make_float4(-1e30f, -1e30f, -1e30f, -1e30f);
#pragma unroll
    for (int o = 0; o < OC; o++) {
        float4 x = *(const float4*)&g_sigma[((size_t)n * OC + o) * HW + pix];
        float sc = g_rstd[o] * __ldg(&gamma[o]);
        float m  = g_mean[o], b = __ldg(&beta[o]);
        x.x = (x.x - m) * sc + b; x.y = (x.y - m) * sc + b;
        x.z = (x.z - m) * sc + b; x.w = (x.w - m) * sc + b;
        s4[o] = x;
        mx.x = fmaxf(mx.x, x.x); mx.y = fmaxf(mx.y, x.y);
        mx.z = fmaxf(mx.z, x.z); mx.w = fmaxf(mx.w, x.w);
    }
    float4 sum = make_float4(0.f, 0.f, 0.f, 0.f);
#pragma unroll
    for (int o = 0; o < OC; o++) {
        s4[o].x = __expf(s4[o].x - mx.x); sum.x += s4[o].x;
        s4[o].y = __expf(s4[o].y - mx.y); sum.y += s4[o].y;
        s4[o].z = __expf(s4[o].z - mx.z); sum.z += s4[o].z;
        s4[o].w = __expf(s4[o].w - mx.w); sum.w += s4[o].w;
    }
    float4 inv = make_float4(1.f / sum.x, 1.f / sum.y, 1.f / sum.z, 1.f / sum.w);
#pragma unroll
    for (int o = 0; o < OC; o++) {
        s4[o].x *= inv.x; s4[o].y *= inv.y; s4[o].z *= inv.z; s4[o].w *= inv.w;
    }

    float* vmap = out + (size_t)NN * CC * HW;
#pragma unroll
    for (int o = 0; o < OC; o++)
        *(float4*)&vmap[((size_t)n * OC + o) * HW + pix] = s4[o];

    int rh[3];
#pragma unroll
    for (int i = 0; i < 3; i++) rh[i] = refl(h0 + i - 1, HH);
    int wl = refl(w0 - 1, WW);
    int wr = refl(w0 + 4, WW);

#pragma unroll
    for (int g = 0; g < 2; g++) {
#pragma unroll 2
        for (int cg = 0; cg < 32; cg++) {
            int c = g * 32 + cg;
            const float* yc = y + ((size_t)(n * CC + c)) * HW;
            float4 acc = make_float4(0.f, 0.f, 0.f, 0.f);
#pragma unroll
            for (int i = 0; i < 3; i++) {
                const float* row = yc + rh[i] * WW;
                float4 m = __ldg((const float4*)(row + w0));
                float v[6];
                v[0] = __ldg(&row[wl]); v[1] = m.x; v[2] = m.y;
                v[3] = m.z; v[4] = m.w; v[5] = __ldg(&row[wr]);
#pragma unroll
                for (int j = 0; j < 3; j++) {
                    float4 sw = s4[g * 9 + i * 3 + j];
                    acc.x += v[0 + j] * sw.x;
                    acc.y += v[1 + j] * sw.y;
                    acc.z += v[2 + j] * sw.z;
                    acc.w += v[3 + j] * sw.w;
                }
            }
            *(float4*)&out[((size_t)(n * CC + c)) * HW + pix] = acc;
        }
    }
}

extern "C" void kernel_launch(void* const* d_in, const int* in_sizes, int n_in,
                              void* d_out, int out_size) {
    const float* y     = (const float*)d_in[0];
    const float* w     = (const float*)d_in[1];
    const float* gamma = (const float*)d_in[2];
    const float* beta  = (const float*)d_in[3];
    float* out = (float*)d_out;

    k_wprep<<<30, 256>>>(w);

    dim3 cgrd(WW / 128, HH, NN);        // 2 x 256 x 4 = 2048 CTAs
    k_conv<<<cgrd, 128>>>(y);

    k_sigred<<<dim3(OC, 32), 256>>>();
    k_stats<<<1, 32>>>();

    dim3 ablk(32, 4), agrd(WW / 128, HH / 4, NN);
    k_apply<<<agrd, ablk>>>(y, gamma, beta, out);
}

// round 11
// speedup vs baseline: 1.2964x; 1.0908x over previous
#include <cuda_runtime.h>
#include <math.h>

#define NN 4
#define CC 64
#define HH 256
#define WW 256
#define OC 18          // G*K*K
#define HW (HH*WW)
#define EPSF 1e-5f

// Scratch (device globals; zero-initialized at load, kept zero by k_stats).
__device__ float g_sigma[(size_t)NN * OC * HW];   // ~18.9 MB
__device__ float g_sum[OC], g_sumsq[OC], g_mean[OC], g_rstd[OC];

// Pre-split packed weights: pair rows over padded K = 8 kb * 80 (tap 0..9, 8 ch,
// channel-innermost: k = kb*80 + tap*8 + c). uint2 = {hi bf16x2, lo bf16x2}.
__device__ uint2 g_Bp[320 * 24];

// jnp.pad mode='reflect' (mirror, edge not repeated)
__device__ __forceinline__ int refl(int i, int n) {
    return i < 0 ? -i : (i >= n ? 2 * n - 2 - i : i);
}

// split two floats into packed bf16 pairs: hi = truncate-to-bf16 (exact sub),
// lo = RN(residual). Pair low half = v0.
__device__ __forceinline__ uint2 split2(float v0, float v1) {
    unsigned u0 = __float_as_uint(v0), u1 = __float_as_uint(v1);
    unsigned hi;
    asm("prmt.b32 %0, %1, %2, 0x7632;" : "=r"(hi) : "r"(u0), "r"(u1));
    float r0 = v0 - __uint_as_float(u0 & 0xFFFF0000u);
    float r1 = v1 - __uint_as_float(u1 & 0xFFFF0000u);
    unsigned lo;
    asm("cvt.rn.bf16x2.f32 %0, %1, %2;" : "=r"(lo) : "f"(r1), "f"(r0));
    return make_uint2(hi, lo);
}

#define MMA16816(d, a, b0, b1)                                                 \
    asm volatile(                                                              \
        "mma.sync.aligned.m16n8k16.row.col.f32.bf16.bf16.f32 "                 \
        "{%0,%1,%2,%3},{%4,%5,%6,%7},{%8,%9},{%0,%1,%2,%3};"                   \
        : "+f"(d[0]), "+f"(d[1]), "+f"(d[2]), "+f"(d[3])                       \
        : "r"(a[0]), "r"(a[1]), "r"(a[2]), "r"(a[3]), "r"(b0), "r"(b1))

// ---------------------------------------------------------------------------
// Weight prep: B[k][o], k = kb*80 + tap*8 + c (tap 9 = zero pad), split+packed
// as channel pairs: g_Bp[kp2][o], kp2 = kb*40 + tap*4 + cp (c = 2cp, 2cp+1).
// ---------------------------------------------------------------------------
__global__ void k_wprep(const float* __restrict__ w) {
    int idx = blockIdx.x * 256 + threadIdx.x;
    if (idx >= 320 * 24) return;
    int kp2 = idx / 24, o = idx % 24;
    int kb = kp2 / 40, p = kp2 % 40, tap = p / 4, cp = p % 4;
    float v0 = 0.f, v1 = 0.f;
    if (tap < 9 && o < OC) {
        v0 = w[((size_t)o * CC + kb * 8 + 2 * cp) * 9 + tap];
        v1 = w[((size_t)o * CC + kb * 8 + 2 * cp + 1) * 9 + tap];
    }
    g_Bp[idx] = split2(v0, v1);
}

// ---------------------------------------------------------------------------
// Conv via mma.sync bf16 3-term split. CTA = 256 thr, tile = 128w x 4h (512 px).
// SMEM holds pre-split bf16 pairs: ysp[(row*132+col)*4 + cp] = {hi,lo} for
// channels (2cp, 2cp+1) at staged (row,col). A fragment reg = 1 LDS.64.
// Warp w: pixels [w*64, w*64+64) = 4 m16 tiles; 3 n8 tiles (24 outs).
// K per kb: taps 0..9 (tap9 pad, B=0) x 8 ch = 80 = 5 k16 chunks.
// BN stats fused into epilogue.
// ---------------------------------------------------------------------------
__global__ void __launch_bounds__(256, 2) k_conv(const float* __restrict__ y) {
    __shared__ uint2 ysp[6 * 132 * 4];   // 25344 B
    __shared__ uint2 bsp[40 * 24];       // 7680 B
    __shared__ float ssum[OC], ssq[OC];

    int tid = threadIdx.x;
    int warp = tid >> 5, lane = tid & 31;
    int g = lane >> 2, t = lane & 3;

    int w0 = blockIdx.x * 128;
    int h0 = blockIdx.y * 4;
    int n  = blockIdx.z;

    if (tid < OC) { ssum[tid] = 0.f; ssq[tid] = 0.f; }

    int grow[6];
#pragma unroll
    for (int r = 0; r < 6; r++) grow[r] = refl(h0 - 1 + r, HH) * WW;

    float acc[4][3][4];
#pragma unroll
    for (int a = 0; a < 4; a++)
#pragma unroll
        for (int b = 0; b < 3; b++)
#pragma unroll
            for (int d = 0; d < 4; d++) acc[a][b][d] = 0.f;

    int hh  = warp >> 1;          // warp's pixel row within tile
    int pxb = (warp & 1) * 64;    // warp's pixel-column base

    for (int kb = 0; kb < 8; kb++) {
        __syncthreads();
        // stage B pairs for this k-block
        for (int i = tid; i < 960; i += 256) bsp[i] = g_Bp[kb * 960 + i];
        // stage + split y: 6 rows x 132 cols x 4 channel-pairs
        const float* ybase = y + ((size_t)(n * CC + kb * 8)) * HW;
        for (int i = tid; i < 3168; i += 256) {
            int cp = i & 3, q = i >> 2;
            int row = q / 132, col = q - row * 132;
            int gw = refl(w0 - 1 + col, WW);
            const float* p0 = ybase + (size_t)(2 * cp) * HW + grow[row] + gw;
            float v0 = __ldg(p0), v1 = __ldg(p0 + HW);
            ysp[i] = split2(v0, v1);
        }
        __syncthreads();

#pragma unroll
        for (int ch = 0; ch < 5; ch++) {
            const int tapA = 2 * ch;
            const int tapB = (2 * ch + 1 < 9) ? 2 * ch + 1 : 0;  // ch4: pad (B=0)
            const int trA = tapA / 3, tcA = tapA % 3;
            const int trB = tapB / 3, tcB = tapB % 3;

            int aA = ((hh + trA) * 132 + pxb + g + tcA) * 4 + t;
            int aB = ((hh + trB) * 132 + pxb + g + tcB) * 4 + t;
            int bbase = (ch * 8 + t) * 24 + g;

            uint2 b0[3], b1[3];
#pragma unroll
            for (int nt = 0; nt < 3; nt++) {
                b0[nt] = bsp[bbase + nt * 8];
                b1[nt] = bsp[bbase + 96 + nt * 8];   // +4 pair-rows (k+8)
            }

#pragma unroll
            for (int mt = 0; mt < 4; mt++) {
                int off = mt * 64;
                uint2 x0 = ysp[aA + off];        // (g,   tapA)
                uint2 x1 = ysp[aA + off + 32];   // (g+8, tapA)
                uint2 x2 = ysp[aB + off];        // (g,   tapB)
                uint2 x3 = ysp[aB + off + 32];   // (g+8, tapB)
                unsigned ah[4] = {x0.x, x1.x, x2.x, x3.x};
                unsigned al[4] = {x0.y, x1.y, x2.y, x3.y};
#pragma unroll
                for (int nt = 0; nt < 3; nt++) {
                    MMA16816(acc[mt][nt], ah, b0[nt].x, b1[nt].x);  // hi*hi
                    MMA16816(acc[mt][nt], al, b0[nt].x, b1[nt].x);  // lo*hi
                    MMA16816(acc[mt][nt], ah, b0[nt].y, b1[nt].y);  // hi*lo
                }
            }
        }
    }

    // epilogue: store sigma + fused BN partial sums
    size_t sb = (size_t)n * OC * HW;
#pragma unroll
    for (int mt = 0; mt < 4; mt++)
#pragma unroll
        for (int nt = 0; nt < 3; nt++)
#pragma unroll
            for (int dd = 0; dd < 4; dd++) {
                int o = nt * 8 + 2 * t + (dd & 1);
                if (o < OC) {
                    int p = warp * 64 + mt * 16 + g + ((dd & 2) ? 8 : 0);
                    g_sigma[sb + (size_t)o * HW +
                            (size_t)(h0 + (p >> 7)) * WW + w0 + (p & 127)] =
                        acc[mt][nt][dd];
                }
            }

#pragma unroll
    for (int nt = 0; nt < 3; nt++)
#pragma unroll
        for (int d1 = 0; d1 < 2; d1++) {
            int o = nt * 8 + 2 * t + d1;
            float s = 0.f, q = 0.f;
#pragma unroll
            for (int mt = 0; mt < 4; mt++)
#pragma unroll
                for (int d2 = 0; d2 < 2; d2++) {
                    float v = acc[mt][nt][d2 * 2 + d1];
                    s += v; q += v * v;
                }
#pragma unroll
            for (int m = 4; m <= 16; m <<= 1) {
                s += __shfl_xor_sync(0xffffffffu, s, m);
                q += __shfl_xor_sync(0xffffffffu, q, m);
            }
            if (g == 0 && o < OC) { atomicAdd(&ssum[o], s); atomicAdd(&ssq[o], q); }
        }
    __syncthreads();
    if (tid < OC) { atomicAdd(&g_sum[tid], ssum[tid]); atomicAdd(&g_sumsq[tid], ssq[tid]); }
}

// Stats + self-reset (next graph replay sees zeros again).
__global__ void k_stats() {
    int o = threadIdx.x;
    if (o < OC) {
        float cnt = (float)((size_t)NN * HW);
        float m = g_sum[o] / cnt;
        float v = g_sumsq[o] / cnt - m * m;
        g_mean[o] = m;
        g_rstd[o] = rsqrtf(v + EPSF);
        g_sum[o] = 0.f;
        g_sumsq[o] = 0.f;
    }
}

// ---------------------------------------------------------------------------
// Stage 3: BN + softmax(18) + v_map + adaptive 3x3 filter. 4 pixels/thread.
// ---------------------------------------------------------------------------
__global__ void __launch_bounds__(128) k_apply(const float* __restrict__ y,
                                               const float* __restrict__ gamma,
                                               const float* __restrict__ beta,
                                               float* __restrict__ out) {
    int tx = threadIdx.x, ty = threadIdx.y;
    int w0 = (blockIdx.x * 32 + tx) * 4;
    int h0 = blockIdx.y * 4 + ty;
    int n  = blockIdx.z;
    size_t pix = (size_t)h0 * WW + w0;

    float4 s4[OC];
    float4 mx = make_float4(-1e30f, -1e30f, -1e30f, -1e30f);
#pragma unroll
    for (int o = 0; o < OC; o++) {
        float4 x = *(const float4*)&g_sigma[((size_t)n * OC + o) * HW + pix];
        float sc = g_rstd[o] * __ldg(&gamma[o]);
        float m  = g_mean[o], b = __ldg(&beta[o]);
        x.x = (x.x - m) * sc + b; x.y = (x.y - m) * sc + b;
        x.z = (x.z - m) * sc + b; x.w = (x.w - m) * sc + b;
        s4[o] = x;
        mx.x = fmaxf(mx.x, x.x); mx.y = fmaxf(mx.y, x.y);
        mx.z = fmaxf(mx.z, x.z); mx.w = fmaxf(mx.w, x.w);
    }
    float4 sum = make_float4(0.f, 0.f, 0.f, 0.f);
#pragma unroll
    for (int o = 0; o < OC; o++) {
        s4[o].x = __expf(s4[o].x - mx.x); sum.x += s4[o].x;
        s4[o].y = __expf(s4[o].y - mx.y); sum.y += s4[o].y;
        s4[o].z = __expf(s4[o].z - mx.z); sum.z += s4[o].z;
        s4[o].w = __expf(s4[o].w - mx.w); sum.w += s4[o].w;
    }
    float4 inv = make_float4(1.f / sum.x, 1.f / sum.y, 1.f / sum.z, 1.f / sum.w);
#pragma unroll
    for (int o = 0; o < OC; o++) {
        s4[o].x *= inv.x; s4[o].y *= inv.y; s4[o].z *= inv.z; s4[o].w *= inv.w;
    }

    float* vmap = out + (size_t)NN * CC * HW;
#pragma unroll
    for (int o = 0; o < OC; o++)
        *(float4*)&vmap[((size_t)n * OC + o) * HW + pix] = s4[o];

    int rh[3];
#pragma unroll
    for (int i = 0; i < 3; i++) rh[i] = refl(h0 + i - 1, HH);
    int wl = refl(w0 - 1, WW);
    int wr = refl(w0 + 4, WW);

#pragma unroll
    for (int g = 0; g < 2; g++) {
#pragma unroll 2
        for (int cg = 0; cg < 32; cg++) {
            int c = g * 32 + cg;
            const float* yc = y + ((size_t)(n * CC + c)) * HW;
            float4 acc = make_float4(0.f, 0.f, 0.f, 0.f);
#pragma unroll
            for (int i = 0; i < 3; i++) {
                const float* row = yc + rh[i] * WW;
                float4 m = __ldg((const float4*)(row + w0));
                float v[6];
                v[0] = __ldg(&row[wl]); v[1] = m.x; v[2] = m.y;
                v[3] = m.z; v[4] = m.w; v[5] = __ldg(&row[wr]);
#pragma unroll
                for (int j = 0; j < 3; j++) {
                    float4 sw = s4[g * 9 + i * 3 + j];
                    acc.x += v[0 + j] * sw.x;
                    acc.y += v[1 + j] * sw.y;
                    acc.z += v[2 + j] * sw.z;
                    acc.w += v[3 + j] * sw.w;
                }
            }
            *(float4*)&out[((size_t)(n * CC + c)) * HW + pix] = acc;
        }
    }
}

extern "C" void kernel_launch(void* const* d_in, const int* in_sizes, int n_in,
                              void* d_out, int out_size) {
    const float* y     = (const float*)d_in[0];
    const float* w     = (const float*)d_in[1];
    const float* gamma = (const float*)d_in[2];
    const float* beta  = (const float*)d_in[3];
    float* out = (float*)d_out;

    k_wprep<<<30, 256>>>(w);

    dim3 cgrd(WW / 128, HH / 4, NN);    // 2 x 64 x 4 = 512 CTAs
    k_conv<<<cgrd, 256>>>(y);

    k_stats<<<1, 32>>>();

    dim3 ablk(32, 4), agrd(WW / 128, HH / 4, NN);
    k_apply<<<agrd, ablk>>>(y, gamma, beta, out);
}